// round 2
// baseline (speedup 1.0000x reference)
#include <cuda_runtime.h>
#include <math.h>
#include <stdint.h>

#define NSEQ   1024
#define XDIM   2048
#define NHEADS 16
#define KVH    2
#define GQH    8
#define DH     128
#define QKVW   2560      // 2048 + 256 + 256
#define CDIM   4096      // CMP_BLK * DH
#define SCALE  0.08838834764831845f
#define NEGBIG -1e10f

// ---------------- scratch (device globals; no runtime allocation) ----------------
__device__ __align__(128) float g_xn    [NSEQ*XDIM];
__device__ __align__(128) float g_qkv   [NSEQ*QKVW];
__device__ __align__(128) float g_f     [2*128*CDIM];
__device__ __align__(128) float g_hidden[2*128*CDIM];
__device__ __align__(128) float g_ckv   [256*DH];
__device__ __align__(128) float g_ckfull[KVH*65*DH];
__device__ __align__(128) float g_cvfull[KVH*65*DH];
__device__ __align__(128) float g_cmp   [NHEADS*NSEQ*DH];
__device__ __align__(128) float g_fine  [NHEADS*NSEQ*DH];
__device__ __align__(128) float g_slide [NHEADS*NSEQ*DH];
__device__ __align__(128) float g_qrope [NHEADS*NSEQ*DH];
__device__ __align__(128) float g_krope [KVH*NSEQ*DH];
__device__ __align__(128) float g_gates [NSEQ*48];
__device__ __align__(128) float g_O1    [NSEQ*XDIM];
__device__ __align__(128) float g_ropetab[NSEQ*64*2];
__device__ int g_sel[KVH*NSEQ*5];

// ---------------- helpers ----------------
__device__ __forceinline__ float warp_sum(float v){
    #pragma unroll
    for (int o = 16; o > 0; o >>= 1) v += __shfl_xor_sync(0xffffffffu, v, o);
    return v;
}
__device__ __forceinline__ float warp_max(float v){
    #pragma unroll
    for (int o = 16; o > 0; o >>= 1) v = fmaxf(v, __shfl_xor_sync(0xffffffffu, v, o));
    return v;
}

// ---------------- rmsnorm ----------------
__global__ void rmsnorm_kernel(const float* __restrict__ x, const float* __restrict__ g){
    int n = blockIdx.x, tid = threadIdx.x;
    const float4* row = (const float4*)(x + (size_t)n*XDIM);
    float s = 0.f;
    for (int i = tid; i < XDIM/4; i += 256){
        float4 v = row[i];
        s += v.x*v.x + v.y*v.y + v.z*v.z + v.w*v.w;
    }
    s = warp_sum(s);
    __shared__ float red[8];
    __shared__ float tot;
    if ((tid & 31) == 0) red[tid >> 5] = s;
    __syncthreads();
    if (tid < 32){
        float v = (tid < 8) ? red[tid] : 0.f;
        v = warp_sum(v);
        if (tid == 0) tot = rsqrtf(v / (float)XDIM + 1e-6f);
    }
    __syncthreads();
    float inv = tot;
    const float4* gg = (const float4*)g;
    float4* op = (float4*)(g_xn + (size_t)n*XDIM);
    for (int i = tid; i < XDIM/4; i += 256){
        float4 v = row[i], w = gg[i], o;
        o.x = v.x*inv*w.x; o.y = v.y*inv*w.y; o.z = v.z*inv*w.z; o.w = v.w*inv*w.w;
        op[i] = o;
    }
}

// ---------------- generic SGEMM: C = op(A@B + bias); tile 128x64x8, micro 8x4 ----
__global__ void sgemm_kernel(const float* __restrict__ A,
                             const float* __restrict__ B0, const float* __restrict__ B1,
                             const float* __restrict__ bias0, const float* __restrict__ bias1,
                             float* __restrict__ C,
                             int M, int N, int K, int op, size_t sA, size_t sC){
    const float* B    = blockIdx.z ? B1    : B0;
    const float* bias = blockIdx.z ? bias1 : bias0;
    A += (size_t)blockIdx.z * sA;
    C += (size_t)blockIdx.z * sC;

    __shared__ float As[8][128];
    __shared__ float Bs[8][64];

    int tid = threadIdx.x;
    int bm = blockIdx.y * 128, bn = blockIdx.x * 64;
    int am = tid >> 1, ak = (tid & 1) * 4;
    int bk = tid >> 5, bn2 = (tid & 31) * 2;
    int ty8 = (tid >> 4) * 8, tx4 = (tid & 15) * 4;

    float acc[8][4];
    #pragma unroll
    for (int i = 0; i < 8; i++)
        #pragma unroll
        for (int j = 0; j < 4; j++) acc[i][j] = 0.f;

    const float* Aptr = A + (size_t)(bm + am)*K + ak;
    const float* Bptr = B + (size_t)bk*N + bn + bn2;
    bool bok2 = (bn + bn2 + 1) < N;
    bool bok1 = (bn + bn2) < N;

    for (int k0 = 0; k0 < K; k0 += 8){
        float4 av = *(const float4*)(Aptr + k0);
        As[ak+0][am] = av.x; As[ak+1][am] = av.y; As[ak+2][am] = av.z; As[ak+3][am] = av.w;
        float bx = 0.f, by = 0.f;
        if (bok2){ float2 bv = *(const float2*)(Bptr + (size_t)k0*N); bx = bv.x; by = bv.y; }
        else if (bok1){ bx = Bptr[(size_t)k0*N]; }
        Bs[bk][bn2] = bx; Bs[bk][bn2+1] = by;
        __syncthreads();
        #pragma unroll
        for (int kk = 0; kk < 8; kk++){
            float a[8], b[4];
            #pragma unroll
            for (int i = 0; i < 8; i++) a[i] = As[kk][ty8 + i];
            #pragma unroll
            for (int j = 0; j < 4; j++) b[j] = Bs[kk][tx4 + j];
            #pragma unroll
            for (int i = 0; i < 8; i++)
                #pragma unroll
                for (int j = 0; j < 4; j++) acc[i][j] += a[i] * b[j];
        }
        __syncthreads();
    }
    #pragma unroll
    for (int i = 0; i < 8; i++){
        int row = bm + ty8 + i;
        #pragma unroll
        for (int j = 0; j < 4; j++){
            int col = bn + tx4 + j;
            if (col < N){
                float v = acc[i][j];
                if (bias) v += bias[col];
                if (op == 1) v = fmaxf(v, 0.f);
                else if (op == 2) v = 1.f / (1.f + __expf(-v));
                C[(size_t)row*N + col] = v;
            }
        }
    }
}

// ---------------- build compressed-window MLP inputs ----------------
__global__ void build_windows_kernel(const float* __restrict__ k_pos,
                                     const float* __restrict__ v_pos){
    int idx = blockIdx.x * 256 + threadIdx.x;   // 2^20 total
    int d = idx & 127;
    int j = (idx >> 7) & 31;
    int w = (idx >> 12) & 63;
    int h = (idx >> 18) & 1;
    int s = (idx >> 19) & 1;
    int t = w*16 + j - 16;
    const float* pos = s ? v_pos : k_pos;
    float pv = pos[(h*32 + j)*128 + d];
    float val = 0.f;
    if (t >= 0) val = g_qkv[(size_t)t*QKVW + (s ? 2304 : 2048) + h*128 + d];
    g_f[(size_t)s*(128*CDIM) + (size_t)(h*64 + w)*CDIM + j*128 + d] = val + pv;
}

// ---------------- MLP2: 256 rows x 128 cols, K=4096 ----------------
__global__ void mlp2_kernel(const float* __restrict__ Wk2, const float* __restrict__ bk2,
                            const float* __restrict__ Wv2, const float* __restrict__ bv2){
    int r0 = blockIdx.x * 4;
    int c  = threadIdx.x;          // 0..127
    const float* B    = (r0 < 128) ? Wk2 : Wv2;
    const float* bias = (r0 < 128) ? bk2 : bv2;
    __shared__ __align__(16) float s_a[4][1024];
    float acc[4] = {0.f, 0.f, 0.f, 0.f};
    for (int kc = 0; kc < 4096; kc += 1024){
        #pragma unroll
        for (int i = 0; i < 8; i++){
            int idx = i*128 + threadIdx.x;  // float4 index 0..1023
            int rr = idx >> 8, cc = idx & 255;
            float4 v = *((const float4*)(g_hidden + (size_t)(r0 + rr)*4096 + kc) + cc);
            *((float4*)&s_a[rr][cc*4]) = v;
        }
        __syncthreads();
        #pragma unroll 4
        for (int k = 0; k < 1024; k++){
            float b = B[(size_t)(kc + k)*128 + c];
            acc[0] += s_a[0][k]*b; acc[1] += s_a[1][k]*b;
            acc[2] += s_a[2][k]*b; acc[3] += s_a[3][k]*b;
        }
        __syncthreads();
    }
    #pragma unroll
    for (int i = 0; i < 4; i++)
        g_ckv[(size_t)(r0 + i)*128 + c] = acc[i] + bias[c];
}

// ---------------- prepend mem_kv ----------------
__global__ void assemble_kernel(const float* __restrict__ mem_kv){
    int b = blockIdx.x;            // 0..259
    int d = threadIdx.x;           // 0..127
    int s = b / 130, hj = b % 130, h = hj / 65, j = hj % 65;
    float v;
    if (j == 0) v = mem_kv[(s*2 + h)*128 + d];
    else        v = g_ckv[(size_t)(s*128 + h*64 + (j-1))*128 + d];
    (s ? g_cvfull : g_ckfull)[(h*65 + j)*128 + d] = v;
}

// ---------------- compressed attention + importance + top-k selection ----------------
__global__ void cmp_attn_kernel(){
    int n = blockIdx.x, h = blockIdx.y;
    int warp = threadIdx.x >> 5, lane = threadIdx.x & 31;
    __shared__ float s_l[8][65];
    __shared__ float s_imp[16];

    const float* q = g_qkv + (size_t)n*QKVW + (h*GQH + warp)*DH;
    float4 qv = *(const float4*)(q + lane*4);

    #pragma unroll 4
    for (int j = 0; j < 65; j++){
        float4 kv = *(const float4*)(g_ckfull + (size_t)(h*65 + j)*DH + lane*4);
        float p = qv.x*kv.x + qv.y*kv.y + qv.z*kv.z + qv.w*kv.w;
        p = warp_sum(p);
        if (lane == 0) s_l[warp][j] = p * SCALE;
    }
    __syncthreads();

    if (threadIdx.x < 16){
        int f = threadIdx.x;
        float s = 0.f;
        #pragma unroll
        for (int g = 0; g < 8; g++)
            #pragma unroll
            for (int w = 0; w < 4; w++) s += s_l[g][1 + f*4 + w];
        s *= (1.f / 32.f);
        if ((n >> 6) == f) s = NEGBIG;
        s_imp[f] = s;
    }
    __syncthreads();

    if (threadIdx.x == 0){
        unsigned used = 0;
        int base = (h*NSEQ + n)*5;
        for (int r = 0; r < 4; r++){
            float best = -3.4e38f; int bi = 0;
            for (int f = 0; f < 16; f++)
                if (!((used >> f) & 1) && s_imp[f] > best){ best = s_imp[f]; bi = f; }
            used |= 1u << bi;
            g_sel[base + r] = bi;
        }
        g_sel[base + 4] = n >> 6;
    }

    float m = -3.4e38f;
    for (int j = lane; j < 65; j += 32) m = fmaxf(m, s_l[warp][j]);
    m = warp_max(m);
    float sum = 0.f;
    for (int j = lane; j < 65; j += 32){
        float e = __expf(s_l[warp][j] - m);
        s_l[warp][j] = e; sum += e;
    }
    sum = warp_sum(sum);
    float inv = 1.f / sum;

    float a0 = 0.f, a1 = 0.f, a2 = 0.f, a3 = 0.f;
    #pragma unroll 4
    for (int j = 0; j < 65; j++){
        float p = s_l[warp][j];
        float4 vv = *(const float4*)(g_cvfull + (size_t)(h*65 + j)*DH + lane*4);
        a0 += p*vv.x; a1 += p*vv.y; a2 += p*vv.z; a3 += p*vv.w;
    }
    float* o = g_cmp + ((size_t)(h*GQH + warp)*NSEQ + n)*DH + lane*4;
    o[0] = a0*inv; o[1] = a1*inv; o[2] = a2*inv; o[3] = a3*inv;
}

// ---------------- RoPE table (fp64) + apply ----------------
__global__ void ropetab_kernel(){
    int idx = blockIdx.x * 256 + threadIdx.x;    // 65536
    int i = idx & 63, n = idx >> 6;
    double f = exp(-((double)(2*i) / 128.0) * 9.210340371976184);
    double ang = (double)n * f;
    g_ropetab[idx*2 + 0] = (float)cos(ang);
    g_ropetab[idx*2 + 1] = (float)sin(ang);
}

__global__ void rope_kernel(){
    int n = blockIdx.x, hh = blockIdx.y, i = threadIdx.x;   // pair index 0..63
    float c = g_ropetab[(n*64 + i)*2 + 0];
    float s = g_ropetab[(n*64 + i)*2 + 1];
    const float* src; float* dst;
    if (hh < 16){
        src = g_qkv + (size_t)n*QKVW + hh*DH;
        dst = g_qrope + ((size_t)hh*NSEQ + n)*DH;
    } else {
        int h = hh - 16;
        src = g_qkv + (size_t)n*QKVW + 2048 + h*DH;
        dst = g_krope + ((size_t)h*NSEQ + n)*DH;
    }
    float x1 = src[2*i], x2 = src[2*i + 1];
    dst[2*i]     = x1*c - x2*s;
    dst[2*i + 1] = x1*s + x2*c;
}

// ---------------- fine (selected-block) attention ----------------
__global__ void fine_attn_kernel(){
    int n = blockIdx.x, h = blockIdx.y;
    int tid = threadIdx.x, warp = tid >> 5, lane = tid & 31;
    __shared__ __align__(16) float s_p[320][8];
    __shared__ int s_blk[5];
    if (tid < 5) s_blk[tid] = g_sel[(h*NSEQ + n)*5 + tid];
    __syncthreads();

    const float* q = g_qrope + ((size_t)(h*GQH + warp)*NSEQ + n)*DH;
    float4 qv = *(const float4*)(q + lane*4);

    for (int b = 0; b < 5; b++){
        int tok0 = s_blk[b] * 64;
        #pragma unroll 2
        for (int tt = 0; tt < 64; tt++){
            float4 kv = *(const float4*)(g_krope + ((size_t)h*NSEQ + tok0 + tt)*DH + lane*4);
            float p = qv.x*kv.x + qv.y*kv.y + qv.z*kv.z + qv.w*kv.w;
            p = warp_sum(p);
            if (lane == 0) s_p[b*64 + tt][warp] = p * SCALE;
        }
    }
    float m = -3.4e38f;
    for (int t = lane; t < 320; t += 32) m = fmaxf(m, s_p[t][warp]);
    m = warp_max(m);
    float sum = 0.f;
    for (int t = lane; t < 320; t += 32){
        float e = __expf(s_p[t][warp] - m);
        s_p[t][warp] = e; sum += e;
    }
    sum = warp_sum(sum);
    float inv = 1.f / sum;
    for (int t = lane; t < 320; t += 32) s_p[t][warp] *= inv;
    __syncthreads();

    int d = tid & 127, half = tid >> 7;
    float a[4] = {0.f, 0.f, 0.f, 0.f};
    for (int b = 0; b < 5; b++){
        size_t vbase = (size_t)s_blk[b]*64*QKVW + 2304 + h*DH + d;
        #pragma unroll 2
        for (int tt = 0; tt < 64; tt++){
            float v = g_qkv[vbase + (size_t)tt*QKVW];
            float4 p = *(const float4*)&s_p[b*64 + tt][half*4];
            a[0] += p.x*v; a[1] += p.y*v; a[2] += p.z*v; a[3] += p.w*v;
        }
    }
    #pragma unroll
    for (int gg = 0; gg < 4; gg++)
        g_fine[((size_t)(h*GQH + half*4 + gg)*NSEQ + n)*DH + d] = a[gg];
}

// ---------------- sliding-window attention (|dq-dk| <= 128) ----------------
__global__ void slide_attn_kernel(){
    int n = blockIdx.x, h = blockIdx.y;
    int tid = threadIdx.x, warp = tid >> 5, lane = tid & 31;
    __shared__ __align__(16) float s_p[257][8];
    int lo = n - 128; if (lo < 0) lo = 0;
    int hi = n + 128; if (hi > NSEQ - 1) hi = NSEQ - 1;
    int cnt = hi - lo + 1;

    const float* q = g_qrope + ((size_t)(h*GQH + warp)*NSEQ + n)*DH;
    float4 qv = *(const float4*)(q + lane*4);

    #pragma unroll 2
    for (int t = 0; t < cnt; t++){
        float4 kv = *(const float4*)(g_krope + ((size_t)h*NSEQ + lo + t)*DH + lane*4);
        float p = qv.x*kv.x + qv.y*kv.y + qv.z*kv.z + qv.w*kv.w;
        p = warp_sum(p);
        if (lane == 0) s_p[t][warp] = p * SCALE;
    }
    float m = -3.4e38f;
    for (int t = lane; t < cnt; t += 32) m = fmaxf(m, s_p[t][warp]);
    m = warp_max(m);
    float sum = 0.f;
    for (int t = lane; t < cnt; t += 32){
        float e = __expf(s_p[t][warp] - m);
        s_p[t][warp] = e; sum += e;
    }
    sum = warp_sum(sum);
    float inv = 1.f / sum;
    for (int t = lane; t < cnt; t += 32) s_p[t][warp] *= inv;
    __syncthreads();

    int d = tid & 127, half = tid >> 7;
    float a[4] = {0.f, 0.f, 0.f, 0.f};
    size_t vbase = (size_t)lo*QKVW + 2304 + h*DH + d;
    #pragma unroll 2
    for (int t = 0; t < cnt; t++){
        float v = g_qkv[vbase + (size_t)t*QKVW];
        float4 p = *(const float4*)&s_p[t][half*4];
        a[0] += p.x*v; a[1] += p.y*v; a[2] += p.z*v; a[3] += p.w*v;
    }
    #pragma unroll
    for (int gg = 0; gg < 4; gg++)
        g_slide[((size_t)(h*GQH + half*4 + gg)*NSEQ + n)*DH + d] = a[gg];
}

// ---------------- gate-weighted combine ----------------
__global__ void combine_kernel(){
    int n = blockIdx.x, hq = blockIdx.y, d = threadIdx.x;
    float g0 = g_gates[n*48 + hq*3 + 0];
    float g1 = g_gates[n*48 + hq*3 + 1];
    float g2 = g_gates[n*48 + hq*3 + 2];
    size_t idx = ((size_t)hq*NSEQ + n)*DH + d;
    g_O1[(size_t)n*XDIM + hq*DH + d] =
        g_cmp[idx]*g0 + g_fine[idx]*g1 + g_slide[idx]*g2;
}

// ---------------- launch ----------------
extern "C" void kernel_launch(void* const* d_in, const int* in_sizes, int n_in,
                              void* d_out, int out_size){
    const float* x      = (const float*)d_in[0];
    const float* g_norm = (const float*)d_in[1];
    const float* W_qkv  = (const float*)d_in[2];
    const float* k_pos  = (const float*)d_in[3];
    const float* v_pos  = (const float*)d_in[4];
    const float* mem_kv = (const float*)d_in[5];
    const float* Wk1    = (const float*)d_in[6];
    const float* bk1    = (const float*)d_in[7];
    const float* Wk2    = (const float*)d_in[8];
    const float* bk2    = (const float*)d_in[9];
    const float* Wv1    = (const float*)d_in[10];
    const float* bv1    = (const float*)d_in[11];
    const float* Wv2    = (const float*)d_in[12];
    const float* bv2    = (const float*)d_in[13];
    const float* Wg     = (const float*)d_in[14];
    const float* bg     = (const float*)d_in[15];
    const float* W_out  = (const float*)d_in[16];
    float* out = (float*)d_out;

    float *p_xn, *p_qkv, *p_f, *p_hidden, *p_gates, *p_O1;
    cudaGetSymbolAddress((void**)&p_xn,     g_xn);
    cudaGetSymbolAddress((void**)&p_qkv,    g_qkv);
    cudaGetSymbolAddress((void**)&p_f,      g_f);
    cudaGetSymbolAddress((void**)&p_hidden, g_hidden);
    cudaGetSymbolAddress((void**)&p_gates,  g_gates);
    cudaGetSymbolAddress((void**)&p_O1,     g_O1);

    rmsnorm_kernel<<<NSEQ, 256>>>(x, g_norm);

    // qkv = xn @ W_qkv : 1024 x 2560 x 2048
    sgemm_kernel<<<dim3(QKVW/64, NSEQ/128, 1), 256>>>(
        p_xn, W_qkv, W_qkv, nullptr, nullptr, p_qkv,
        NSEQ, QKVW, XDIM, 0, 0, 0);

    ropetab_kernel<<<256, 256>>>();
    build_windows_kernel<<<4096, 256>>>(k_pos, v_pos);

    // MLP1 (k & v batched): relu(f @ W1 + b1) : (128 x 4096 x 4096) x2
    sgemm_kernel<<<dim3(CDIM/64, 1, 2), 256>>>(
        p_f, Wk1, Wv1, bk1, bv1, p_hidden,
        128, CDIM, CDIM, 1, (size_t)128*CDIM, (size_t)128*CDIM);

    mlp2_kernel<<<64, 128>>>(Wk2, bk2, Wv2, bv2);
    assemble_kernel<<<260, 128>>>(mem_kv);

    cmp_attn_kernel<<<dim3(NSEQ, KVH), 256>>>();
    rope_kernel<<<dim3(NSEQ, 18), 64>>>();
    fine_attn_kernel<<<dim3(NSEQ, KVH), 256>>>();
    slide_attn_kernel<<<dim3(NSEQ, KVH), 256>>>();

    // gates = sigmoid(xn @ Wg + bg) : 1024 x 48 x 2048
    sgemm_kernel<<<dim3(1, NSEQ/128, 1), 256>>>(
        p_xn, Wg, Wg, bg, bg, p_gates,
        NSEQ, 48, XDIM, 2, 0, 0);

    combine_kernel<<<dim3(NSEQ, NHEADS), 128>>>();

    // out = O1 @ W_out : 1024 x 2048 x 2048
    sgemm_kernel<<<dim3(XDIM/64, NSEQ/128, 1), 256>>>(
        p_O1, W_out, W_out, nullptr, nullptr, out,
        NSEQ, XDIM, XDIM, 0, 0, 0);
}

// round 3
// speedup vs baseline: 1.1482x; 1.1482x over previous
#include <cuda_runtime.h>
#include <math.h>
#include <stdint.h>

#define NSEQ   1024
#define XDIM   2048
#define NHEADS 16
#define KVH    2
#define GQH    8
#define DH     128
#define QKVW   2560      // 2048 + 256 + 256
#define CDIM   4096      // CMP_BLK * DH
#define SCALE  0.08838834764831845f
#define NEGBIG -1e10f

// ---------------- scratch (device globals; no runtime allocation) ----------------
__device__ __align__(128) float g_xn    [NSEQ*XDIM];
__device__ __align__(128) float g_qkv   [NSEQ*QKVW];
__device__ __align__(128) float g_f     [2*128*CDIM];
__device__ __align__(128) float g_hidden[2*128*CDIM];
__device__ __align__(128) float g_ckv   [256*DH];
__device__ __align__(128) float g_ckfull[KVH*65*DH];
__device__ __align__(128) float g_cvfull[KVH*65*DH];
__device__ __align__(128) float g_cmp   [NHEADS*NSEQ*DH];
__device__ __align__(128) float g_fine  [NHEADS*NSEQ*DH];
__device__ __align__(128) float g_slide [NHEADS*NSEQ*DH];
__device__ __align__(128) float g_qrope [NHEADS*NSEQ*DH];
__device__ __align__(128) float g_krope [KVH*NSEQ*DH];
__device__ __align__(128) float g_O1    [NSEQ*XDIM];
__device__ __align__(128) float g_ropetab[NSEQ*64*2];
__device__ __align__(128) float g_gpart [16*NSEQ*48];
__device__ int g_sel[KVH*NSEQ*5];

// ---------------- helpers ----------------
__device__ __forceinline__ float warp_sum(float v){
    #pragma unroll
    for (int o = 16; o > 0; o >>= 1) v += __shfl_xor_sync(0xffffffffu, v, o);
    return v;
}
__device__ __forceinline__ float warp_max(float v){
    #pragma unroll
    for (int o = 16; o > 0; o >>= 1) v = fmaxf(v, __shfl_xor_sync(0xffffffffu, v, o));
    return v;
}
__device__ __forceinline__ float tf32r(float x){
    unsigned r; asm("cvt.rna.tf32.f32 %0, %1;" : "=r"(r) : "f"(x));
    return __uint_as_float(r);
}
__device__ __forceinline__ void mma8(float* d, const unsigned* a, const unsigned* b){
    asm volatile("mma.sync.aligned.m16n8k8.row.col.f32.tf32.tf32.f32 "
        "{%0,%1,%2,%3},{%4,%5,%6,%7},{%8,%9},{%0,%1,%2,%3};"
        : "+f"(d[0]),"+f"(d[1]),"+f"(d[2]),"+f"(d[3])
        : "r"(a[0]),"r"(a[1]),"r"(a[2]),"r"(a[3]),"r"(b[0]),"r"(b[1]));
}

// ---------------- rmsnorm ----------------
__global__ void rmsnorm_kernel(const float* __restrict__ x, const float* __restrict__ g){
    int n = blockIdx.x, tid = threadIdx.x;
    const float4* row = (const float4*)(x + (size_t)n*XDIM);
    float s = 0.f;
    for (int i = tid; i < XDIM/4; i += 256){
        float4 v = row[i];
        s += v.x*v.x + v.y*v.y + v.z*v.z + v.w*v.w;
    }
    s = warp_sum(s);
    __shared__ float red[8];
    __shared__ float tot;
    if ((tid & 31) == 0) red[tid >> 5] = s;
    __syncthreads();
    if (tid < 32){
        float v = (tid < 8) ? red[tid] : 0.f;
        v = warp_sum(v);
        if (tid == 0) tot = rsqrtf(v / (float)XDIM + 1e-6f);
    }
    __syncthreads();
    float inv = tot;
    const float4* gg = (const float4*)g;
    float4* op = (float4*)(g_xn + (size_t)n*XDIM);
    for (int i = tid; i < XDIM/4; i += 256){
        float4 v = row[i], w = gg[i], o;
        o.x = v.x*inv*w.x; o.y = v.y*inv*w.y; o.z = v.z*inv*w.z; o.w = v.w*inv*w.w;
        op[i] = o;
    }
}

// ---------------- TF32 tensor-core GEMM ----------------
// C[MxN] = op(A[MxK] @ B[KxN] + bias). Block tile 128x128, 8 warps (warp 64x32),
// k-step 8, double buffered. SPLIT=true: 3xTF32 (near-fp32 accuracy).
// Requires M%128==0 (or M==128), N%128==0, K%8==0.
template<bool SPLIT>
__global__ __launch_bounds__(256)
void tf32_gemm(const float* __restrict__ A,
               const float* __restrict__ B0, const float* __restrict__ B1,
               const float* __restrict__ bias0, const float* __restrict__ bias1,
               float* __restrict__ C,
               int M, int N, int K, int relu, size_t sA, size_t sC){
    const float* B    = blockIdx.z ? B1    : B0;
    const float* bias = blockIdx.z ? bias1 : bias0;
    A += (size_t)blockIdx.z * sA;
    C += (size_t)blockIdx.z * sC;

    __shared__ float Ash[2][8][132];
    __shared__ float Bsh[2][8][132];
    __shared__ float Asl[2][8][132];
    __shared__ float Bsl[2][8][132];

    int tid = threadIdx.x, lane = tid & 31, warp = tid >> 5;
    int bm = blockIdx.y * 128, bn = blockIdx.x * 128;
    int wm = (warp & 1) * 64, wn = (warp >> 1) * 32;
    int gid = lane >> 2, tig = lane & 3;

    // global load mapping
    int arow = tid >> 1, ak4 = (tid & 1) * 4;     // A: 128 rows x 8 k
    int bkr  = tid >> 5, bn4 = (tid & 31) * 4;    // B: 8 k x 128 n

    const float* Aptr = A + (size_t)(bm + arow)*K + ak4;
    const float* Bptr = B + (size_t)bkr*N + bn + bn4;

    float acc[4][4][4];
    #pragma unroll
    for (int i = 0; i < 4; i++)
        #pragma unroll
        for (int j = 0; j < 4; j++)
            #pragma unroll
            for (int e = 0; e < 4; e++) acc[i][j][e] = 0.f;

    // prologue: load k0=0 into buf 0
    {
        float4 av = *(const float4*)Aptr;
        float4 bv = *(const float4*)Bptr;
        float a[4] = {av.x, av.y, av.z, av.w};
        float b[4] = {bv.x, bv.y, bv.z, bv.w};
        #pragma unroll
        for (int i = 0; i < 4; i++){
            float h = tf32r(a[i]);
            Ash[0][ak4 + i][arow] = h;
            if (SPLIT) Asl[0][ak4 + i][arow] = tf32r(a[i] - h);
        }
        #pragma unroll
        for (int i = 0; i < 4; i++){
            float h = tf32r(b[i]);
            Bsh[0][bkr][bn4 + i] = h;
            if (SPLIT) Bsl[0][bkr][bn4 + i] = tf32r(b[i] - h);
        }
    }
    __syncthreads();

    int buf = 0;
    for (int k0 = 0; k0 < K; k0 += 8){
        bool more = (k0 + 8) < K;
        float4 av, bv;
        if (more){
            av = *(const float4*)(Aptr + k0 + 8);
            bv = *(const float4*)(Bptr + (size_t)(k0 + 8)*N);
        }

        // compute from buf
        unsigned ah[4][4], bh[4][2];
        unsigned al[4][4], bl[4][2];
        #pragma unroll
        for (int mt = 0; mt < 4; mt++){
            int r = wm + mt*16 + gid;
            ah[mt][0] = __float_as_uint(Ash[buf][tig  ][r]);
            ah[mt][1] = __float_as_uint(Ash[buf][tig  ][r+8]);
            ah[mt][2] = __float_as_uint(Ash[buf][tig+4][r]);
            ah[mt][3] = __float_as_uint(Ash[buf][tig+4][r+8]);
            if (SPLIT){
                al[mt][0] = __float_as_uint(Asl[buf][tig  ][r]);
                al[mt][1] = __float_as_uint(Asl[buf][tig  ][r+8]);
                al[mt][2] = __float_as_uint(Asl[buf][tig+4][r]);
                al[mt][3] = __float_as_uint(Asl[buf][tig+4][r+8]);
            }
        }
        #pragma unroll
        for (int nt = 0; nt < 4; nt++){
            int c = wn + nt*8 + gid;
            bh[nt][0] = __float_as_uint(Bsh[buf][tig  ][c]);
            bh[nt][1] = __float_as_uint(Bsh[buf][tig+4][c]);
            if (SPLIT){
                bl[nt][0] = __float_as_uint(Bsl[buf][tig  ][c]);
                bl[nt][1] = __float_as_uint(Bsl[buf][tig+4][c]);
            }
        }
        #pragma unroll
        for (int mt = 0; mt < 4; mt++)
            #pragma unroll
            for (int nt = 0; nt < 4; nt++){
                if (SPLIT){
                    mma8(acc[mt][nt], ah[mt], bl[nt]);
                    mma8(acc[mt][nt], al[mt], bh[nt]);
                }
                mma8(acc[mt][nt], ah[mt], bh[nt]);
            }

        if (more){
            int nb = buf ^ 1;
            float a[4] = {av.x, av.y, av.z, av.w};
            float b[4] = {bv.x, bv.y, bv.z, bv.w};
            #pragma unroll
            for (int i = 0; i < 4; i++){
                float h = tf32r(a[i]);
                Ash[nb][ak4 + i][arow] = h;
                if (SPLIT) Asl[nb][ak4 + i][arow] = tf32r(a[i] - h);
            }
            #pragma unroll
            for (int i = 0; i < 4; i++){
                float h = tf32r(b[i]);
                Bsh[nb][bkr][bn4 + i] = h;
                if (SPLIT) Bsl[nb][bkr][bn4 + i] = tf32r(b[i] - h);
            }
        }
        __syncthreads();
        buf ^= 1;
    }

    // epilogue
    #pragma unroll
    for (int mt = 0; mt < 4; mt++){
        int row = bm + wm + mt*16 + gid;
        #pragma unroll
        for (int nt = 0; nt < 4; nt++){
            int col = bn + wn + nt*8 + tig*2;
            float b0 = bias ? bias[col]   : 0.f;
            float b1 = bias ? bias[col+1] : 0.f;
            float d0 = acc[mt][nt][0] + b0, d1 = acc[mt][nt][1] + b1;
            float d2 = acc[mt][nt][2] + b0, d3 = acc[mt][nt][3] + b1;
            if (relu){
                d0 = fmaxf(d0, 0.f); d1 = fmaxf(d1, 0.f);
                d2 = fmaxf(d2, 0.f); d3 = fmaxf(d3, 0.f);
            }
            *(float2*)(C + (size_t)row*N + col)     = make_float2(d0, d1);
            *(float2*)(C + (size_t)(row+8)*N + col) = make_float2(d2, d3);
        }
    }
}

// ---------------- gates: split-K partial GEMM (1024 x 48, K=2048) -------------
__global__ void gates_partial_kernel(const float* __restrict__ Wg){
    int ks = blockIdx.x;           // 0..15 -> K chunk of 128
    int bm = blockIdx.y * 128;
    int t = threadIdx.x;
    int rg = t >> 3, cg = t & 7;   // rows rg*4..+3, cols cg*6..+5
    __shared__ float s_a[128][17];
    __shared__ float s_b[16][48];
    float acc[4][6];
    #pragma unroll
    for (int i = 0; i < 4; i++)
        #pragma unroll
        for (int j = 0; j < 6; j++) acc[i][j] = 0.f;
    int k0base = ks * 128;
    for (int kk = 0; kk < 128; kk += 16){
        int row = t >> 1, kh = (t & 1) * 8;
        const float* src = g_xn + (size_t)(bm + row)*XDIM + k0base + kk + kh;
        float4 v0 = *(const float4*)src, v1 = *(const float4*)(src + 4);
        s_a[row][kh+0]=v0.x; s_a[row][kh+1]=v0.y; s_a[row][kh+2]=v0.z; s_a[row][kh+3]=v0.w;
        s_a[row][kh+4]=v1.x; s_a[row][kh+5]=v1.y; s_a[row][kh+6]=v1.z; s_a[row][kh+7]=v1.w;
        #pragma unroll
        for (int i = 0; i < 3; i++){
            int idx = i*256 + t;
            s_b[idx/48][idx%48] = Wg[(size_t)(k0base + kk + idx/48)*48 + idx%48];
        }
        __syncthreads();
        #pragma unroll 4
        for (int k = 0; k < 16; k++){
            float a[4], b[6];
            #pragma unroll
            for (int i = 0; i < 4; i++) a[i] = s_a[rg*4 + i][k];
            #pragma unroll
            for (int j = 0; j < 6; j++) b[j] = s_b[k][cg*6 + j];
            #pragma unroll
            for (int i = 0; i < 4; i++)
                #pragma unroll
                for (int j = 0; j < 6; j++) acc[i][j] += a[i]*b[j];
        }
        __syncthreads();
    }
    #pragma unroll
    for (int i = 0; i < 4; i++)
        #pragma unroll
        for (int j = 0; j < 6; j++)
            g_gpart[(size_t)ks*NSEQ*48 + (size_t)(bm + rg*4 + i)*48 + cg*6 + j] = acc[i][j];
}

// ---------------- build compressed-window MLP inputs ----------------
__global__ void build_windows_kernel(const float* __restrict__ k_pos,
                                     const float* __restrict__ v_pos){
    int idx = blockIdx.x * 256 + threadIdx.x;   // 2^20 total
    int d = idx & 127;
    int j = (idx >> 7) & 31;
    int w = (idx >> 12) & 63;
    int h = (idx >> 18) & 1;
    int s = (idx >> 19) & 1;
    int t = w*16 + j - 16;
    const float* pos = s ? v_pos : k_pos;
    float pv = pos[(h*32 + j)*128 + d];
    float val = 0.f;
    if (t >= 0) val = g_qkv[(size_t)t*QKVW + (s ? 2304 : 2048) + h*128 + d];
    g_f[(size_t)s*(128*CDIM) + (size_t)(h*64 + w)*CDIM + j*128 + d] = val + pv;
}

// ---------------- MLP2: 256 rows x 128 cols, K=4096 ----------------
__global__ void mlp2_kernel(const float* __restrict__ Wk2, const float* __restrict__ bk2,
                            const float* __restrict__ Wv2, const float* __restrict__ bv2){
    int r0 = blockIdx.x * 4;
    int c  = threadIdx.x;          // 0..127
    const float* B    = (r0 < 128) ? Wk2 : Wv2;
    const float* bias = (r0 < 128) ? bk2 : bv2;
    __shared__ __align__(16) float s_a[4][1024];
    float acc[4] = {0.f, 0.f, 0.f, 0.f};
    for (int kc = 0; kc < 4096; kc += 1024){
        #pragma unroll
        for (int i = 0; i < 8; i++){
            int idx = i*128 + threadIdx.x;  // float4 index 0..1023
            int rr = idx >> 8, cc = idx & 255;
            float4 v = *((const float4*)(g_hidden + (size_t)(r0 + rr)*4096 + kc) + cc);
            *((float4*)&s_a[rr][cc*4]) = v;
        }
        __syncthreads();
        #pragma unroll 4
        for (int k = 0; k < 1024; k++){
            float b = B[(size_t)(kc + k)*128 + c];
            acc[0] += s_a[0][k]*b; acc[1] += s_a[1][k]*b;
            acc[2] += s_a[2][k]*b; acc[3] += s_a[3][k]*b;
        }
        __syncthreads();
    }
    #pragma unroll
    for (int i = 0; i < 4; i++)
        g_ckv[(size_t)(r0 + i)*128 + c] = acc[i] + bias[c];
}

// ---------------- prepend mem_kv ----------------
__global__ void assemble_kernel(const float* __restrict__ mem_kv){
    int b = blockIdx.x;            // 0..259
    int d = threadIdx.x;           // 0..127
    int s = b / 130, hj = b % 130, h = hj / 65, j = hj % 65;
    float v;
    if (j == 0) v = mem_kv[(s*2 + h)*128 + d];
    else        v = g_ckv[(size_t)(s*128 + h*64 + (j-1))*128 + d];
    (s ? g_cvfull : g_ckfull)[(h*65 + j)*128 + d] = v;
}

// ---------------- compressed attention + importance + top-k selection ----------------
__global__ void cmp_attn_kernel(){
    int n = blockIdx.x, h = blockIdx.y;
    int warp = threadIdx.x >> 5, lane = threadIdx.x & 31;
    __shared__ float s_l[8][65];
    __shared__ float s_imp[16];

    const float* q = g_qkv + (size_t)n*QKVW + (h*GQH + warp)*DH;
    float4 qv = *(const float4*)(q + lane*4);

    #pragma unroll 4
    for (int j = 0; j < 65; j++){
        float4 kv = *(const float4*)(g_ckfull + (size_t)(h*65 + j)*DH + lane*4);
        float p = qv.x*kv.x + qv.y*kv.y + qv.z*kv.z + qv.w*kv.w;
        p = warp_sum(p);
        if (lane == 0) s_l[warp][j] = p * SCALE;
    }
    __syncthreads();

    if (threadIdx.x < 16){
        int f = threadIdx.x;
        float s = 0.f;
        #pragma unroll
        for (int g = 0; g < 8; g++)
            #pragma unroll
            for (int w = 0; w < 4; w++) s += s_l[g][1 + f*4 + w];
        s *= (1.f / 32.f);
        if ((n >> 6) == f) s = NEGBIG;
        s_imp[f] = s;
    }
    __syncthreads();

    if (threadIdx.x == 0){
        unsigned used = 0;
        int base = (h*NSEQ + n)*5;
        for (int r = 0; r < 4; r++){
            float best = -3.4e38f; int bi = 0;
            for (int f = 0; f < 16; f++)
                if (!((used >> f) & 1) && s_imp[f] > best){ best = s_imp[f]; bi = f; }
            used |= 1u << bi;
            g_sel[base + r] = bi;
        }
        g_sel[base + 4] = n >> 6;
    }

    float m = -3.4e38f;
    for (int j = lane; j < 65; j += 32) m = fmaxf(m, s_l[warp][j]);
    m = warp_max(m);
    float sum = 0.f;
    for (int j = lane; j < 65; j += 32){
        float e = __expf(s_l[warp][j] - m);
        s_l[warp][j] = e; sum += e;
    }
    sum = warp_sum(sum);
    float inv = 1.f / sum;

    float a0 = 0.f, a1 = 0.f, a2 = 0.f, a3 = 0.f;
    #pragma unroll 4
    for (int j = 0; j < 65; j++){
        float p = s_l[warp][j];
        float4 vv = *(const float4*)(g_cvfull + (size_t)(h*65 + j)*DH + lane*4);
        a0 += p*vv.x; a1 += p*vv.y; a2 += p*vv.z; a3 += p*vv.w;
    }
    float* o = g_cmp + ((size_t)(h*GQH + warp)*NSEQ + n)*DH + lane*4;
    o[0] = a0*inv; o[1] = a1*inv; o[2] = a2*inv; o[3] = a3*inv;
}

// ---------------- RoPE table (fp64) + apply ----------------
__global__ void ropetab_kernel(){
    int idx = blockIdx.x * 256 + threadIdx.x;    // 65536
    int i = idx & 63, n = idx >> 6;
    double f = exp(-((double)(2*i) / 128.0) * 9.210340371976184);
    double ang = (double)n * f;
    g_ropetab[idx*2 + 0] = (float)cos(ang);
    g_ropetab[idx*2 + 1] = (float)sin(ang);
}

__global__ void rope_kernel(){
    int n = blockIdx.x, hh = blockIdx.y, i = threadIdx.x;   // pair index 0..63
    float c = g_ropetab[(n*64 + i)*2 + 0];
    float s = g_ropetab[(n*64 + i)*2 + 1];
    const float* src; float* dst;
    if (hh < 16){
        src = g_qkv + (size_t)n*QKVW + hh*DH;
        dst = g_qrope + ((size_t)hh*NSEQ + n)*DH;
    } else {
        int h = hh - 16;
        src = g_qkv + (size_t)n*QKVW + 2048 + h*DH;
        dst = g_krope + ((size_t)h*NSEQ + n)*DH;
    }
    float x1 = src[2*i], x2 = src[2*i + 1];
    dst[2*i]     = x1*c - x2*s;
    dst[2*i + 1] = x1*s + x2*c;
}

// ---------------- fine (selected-block) attention ----------------
__global__ void fine_attn_kernel(){
    int n = blockIdx.x, h = blockIdx.y;
    int tid = threadIdx.x, warp = tid >> 5, lane = tid & 31;
    __shared__ __align__(16) float s_p[320][8];
    __shared__ int s_blk[5];
    if (tid < 5) s_blk[tid] = g_sel[(h*NSEQ + n)*5 + tid];
    __syncthreads();

    const float* q = g_qrope + ((size_t)(h*GQH + warp)*NSEQ + n)*DH;
    float4 qv = *(const float4*)(q + lane*4);

    for (int b = 0; b < 5; b++){
        int tok0 = s_blk[b] * 64;
        #pragma unroll 2
        for (int tt = 0; tt < 64; tt++){
            float4 kv = *(const float4*)(g_krope + ((size_t)h*NSEQ + tok0 + tt)*DH + lane*4);
            float p = qv.x*kv.x + qv.y*kv.y + qv.z*kv.z + qv.w*kv.w;
            p = warp_sum(p);
            if (lane == 0) s_p[b*64 + tt][warp] = p * SCALE;
        }
    }
    float m = -3.4e38f;
    for (int t = lane; t < 320; t += 32) m = fmaxf(m, s_p[t][warp]);
    m = warp_max(m);
    float sum = 0.f;
    for (int t = lane; t < 320; t += 32){
        float e = __expf(s_p[t][warp] - m);
        s_p[t][warp] = e; sum += e;
    }
    sum = warp_sum(sum);
    float inv = 1.f / sum;
    for (int t = lane; t < 320; t += 32) s_p[t][warp] *= inv;
    __syncthreads();

    int d = tid & 127, half = tid >> 7;
    float a[4] = {0.f, 0.f, 0.f, 0.f};
    for (int b = 0; b < 5; b++){
        size_t vbase = (size_t)s_blk[b]*64*QKVW + 2304 + h*DH + d;
        #pragma unroll 2
        for (int tt = 0; tt < 64; tt++){
            float v = g_qkv[vbase + (size_t)tt*QKVW];
            float4 p = *(const float4*)&s_p[b*64 + tt][half*4];
            a[0] += p.x*v; a[1] += p.y*v; a[2] += p.z*v; a[3] += p.w*v;
        }
    }
    #pragma unroll
    for (int gg = 0; gg < 4; gg++)
        g_fine[((size_t)(h*GQH + half*4 + gg)*NSEQ + n)*DH + d] = a[gg];
}

// ---------------- sliding-window attention (|dq-dk| <= 128) ----------------
__global__ void slide_attn_kernel(){
    int n = blockIdx.x, h = blockIdx.y;
    int tid = threadIdx.x, warp = tid >> 5, lane = tid & 31;
    __shared__ __align__(16) float s_p[257][8];
    int lo = n - 128; if (lo < 0) lo = 0;
    int hi = n + 128; if (hi > NSEQ - 1) hi = NSEQ - 1;
    int cnt = hi - lo + 1;

    const float* q = g_qrope + ((size_t)(h*GQH + warp)*NSEQ + n)*DH;
    float4 qv = *(const float4*)(q + lane*4);

    #pragma unroll 2
    for (int t = 0; t < cnt; t++){
        float4 kv = *(const float4*)(g_krope + ((size_t)h*NSEQ + lo + t)*DH + lane*4);
        float p = qv.x*kv.x + qv.y*kv.y + qv.z*kv.z + qv.w*kv.w;
        p = warp_sum(p);
        if (lane == 0) s_p[t][warp] = p * SCALE;
    }
    float m = -3.4e38f;
    for (int t = lane; t < cnt; t += 32) m = fmaxf(m, s_p[t][warp]);
    m = warp_max(m);
    float sum = 0.f;
    for (int t = lane; t < cnt; t += 32){
        float e = __expf(s_p[t][warp] - m);
        s_p[t][warp] = e; sum += e;
    }
    sum = warp_sum(sum);
    float inv = 1.f / sum;
    for (int t = lane; t < cnt; t += 32) s_p[t][warp] *= inv;
    __syncthreads();

    int d = tid & 127, half = tid >> 7;
    float a[4] = {0.f, 0.f, 0.f, 0.f};
    size_t vbase = (size_t)lo*QKVW + 2304 + h*DH + d;
    #pragma unroll 2
    for (int t = 0; t < cnt; t++){
        float v = g_qkv[vbase + (size_t)t*QKVW];
        float4 p = *(const float4*)&s_p[t][half*4];
        a[0] += p.x*v; a[1] += p.y*v; a[2] += p.z*v; a[3] += p.w*v;
    }
    #pragma unroll
    for (int gg = 0; gg < 4; gg++)
        g_slide[((size_t)(h*GQH + half*4 + gg)*NSEQ + n)*DH + d] = a[gg];
}

// ---------------- gate-weighted combine (sums split-K gate partials) ----------
__global__ void combine_kernel(const float* __restrict__ bg){
    int n = blockIdx.x, hq = blockIdx.y, d = threadIdx.x;
    __shared__ float sg[3];
    if (d < 3){
        float s = bg[hq*3 + d];
        #pragma unroll
        for (int p = 0; p < 16; p++)
            s += g_gpart[(size_t)p*NSEQ*48 + (size_t)n*48 + hq*3 + d];
        sg[d] = 1.f / (1.f + __expf(-s));
    }
    __syncthreads();
    float g0 = sg[0], g1 = sg[1], g2 = sg[2];
    size_t idx = ((size_t)hq*NSEQ + n)*DH + d;
    g_O1[(size_t)n*XDIM + hq*DH + d] =
        g_cmp[idx]*g0 + g_fine[idx]*g1 + g_slide[idx]*g2;
}

// ---------------- launch ----------------
extern "C" void kernel_launch(void* const* d_in, const int* in_sizes, int n_in,
                              void* d_out, int out_size){
    const float* x      = (const float*)d_in[0];
    const float* g_norm = (const float*)d_in[1];
    const float* W_qkv  = (const float*)d_in[2];
    const float* k_pos  = (const float*)d_in[3];
    const float* v_pos  = (const float*)d_in[4];
    const float* mem_kv = (const float*)d_in[5];
    const float* Wk1    = (const float*)d_in[6];
    const float* bk1    = (const float*)d_in[7];
    const float* Wk2    = (const float*)d_in[8];
    const float* bk2    = (const float*)d_in[9];
    const float* Wv1    = (const float*)d_in[10];
    const float* bv1    = (const float*)d_in[11];
    const float* Wv2    = (const float*)d_in[12];
    const float* bv2    = (const float*)d_in[13];
    const float* Wg     = (const float*)d_in[14];
    const float* bg     = (const float*)d_in[15];
    const float* W_out  = (const float*)d_in[16];
    float* out = (float*)d_out;

    float *p_xn, *p_qkv, *p_f, *p_hidden, *p_O1;
    cudaGetSymbolAddress((void**)&p_xn,     g_xn);
    cudaGetSymbolAddress((void**)&p_qkv,    g_qkv);
    cudaGetSymbolAddress((void**)&p_f,      g_f);
    cudaGetSymbolAddress((void**)&p_hidden, g_hidden);
    cudaGetSymbolAddress((void**)&p_O1,     g_O1);

    rmsnorm_kernel<<<NSEQ, 256>>>(x, g_norm);

    // qkv = xn @ W_qkv : 1024 x 2560 x 2048 (3xTF32 — feeds selection)
    tf32_gemm<true><<<dim3(QKVW/128, NSEQ/128, 1), 256>>>(
        p_xn, W_qkv, W_qkv, nullptr, nullptr, p_qkv,
        NSEQ, QKVW, XDIM, 0, 0, 0);

    ropetab_kernel<<<256, 256>>>();
    gates_partial_kernel<<<dim3(16, NSEQ/128), 256>>>(Wg);
    build_windows_kernel<<<4096, 256>>>(k_pos, v_pos);

    // MLP1 (k & v batched): relu(f @ W1 + b1) : (128 x 4096 x 4096) x2 (3xTF32)
    tf32_gemm<true><<<dim3(CDIM/128, 1, 2), 256>>>(
        p_f, Wk1, Wv1, bk1, bv1, p_hidden,
        128, CDIM, CDIM, 1, (size_t)128*CDIM, (size_t)128*CDIM);

    mlp2_kernel<<<64, 128>>>(Wk2, bk2, Wv2, bv2);
    assemble_kernel<<<260, 128>>>(mem_kv);

    cmp_attn_kernel<<<dim3(NSEQ, KVH), 256>>>();
    rope_kernel<<<dim3(NSEQ, 18), 64>>>();
    fine_attn_kernel<<<dim3(NSEQ, KVH), 256>>>();
    slide_attn_kernel<<<dim3(NSEQ, KVH), 256>>>();

    combine_kernel<<<dim3(NSEQ, NHEADS), 128>>>(bg);

    // out = O1 @ W_out : 1024 x 2048 x 2048 (plain TF32 — after all decisions)
    tf32_gemm<false><<<dim3(XDIM/128, NSEQ/128, 1), 256>>>(
        p_O1, W_out, W_out, nullptr, nullptr, out,
        NSEQ, XDIM, XDIM, 0, 0, 0);
}